// round 9
// baseline (speedup 1.0000x reference)
#include <cuda_runtime.h>
#include <cuda_fp16.h>
#include <cstdint>

#define DG 128
#define MAXN 100000
#define MAXE 1600000
#define SCB 1024
#define MAXB ((MAXN + SCB - 1) / SCB)

// Scratch (device globals — no allocation allowed).
__device__ int g_deg[MAXN];
__device__ int g_rowptr[MAXN + 1];
__device__ int g_cursor[MAXN];
__device__ int g_csrc[MAXE];
__device__ int g_bsum[MAXB];
__device__ int g_boff[MAXB];
__device__ __align__(16) __half g_hh[MAXN * DG];    // h after layer0+LN (fp16)
__device__ __align__(16) __half g_wh[2 * DG * DG];  // [n][k] fp16 fused weights

// ---------------------------------------------------------------------------
// Prep: zero degree array + fuse/convert weights (merged kernel)
// g_wh[n][k] = fp16( k<128 ? Wl1[k][n] : Wr1[k-128][n] )
// ---------------------------------------------------------------------------
__global__ void prep_kernel(const float* __restrict__ Wl,
                            const float* __restrict__ Wr, int n) {
    int t = blockIdx.x * blockDim.x + threadIdx.x;
    if (t < 2 * DG * DG) {
        int k = t >> 7, nn = t & 127;
        float v = (k < DG) ? Wl[k * DG + nn] : Wr[(k - DG) * DG + nn];
        g_wh[nn * 2 * DG + k] = __float2half_rn(v);
    }
    if (t < n) g_deg[t] = 0;
}

__global__ void hist_kernel(const int* __restrict__ ei, int nE) {
    int e = blockIdx.x * blockDim.x + threadIdx.x;
    if (e < nE) atomicAdd(&g_deg[ei[nE + e]], 1);
}

// Phase 1: per-chunk sums.
__global__ __launch_bounds__(256) void bsum_kernel(int n) {
    int base = blockIdx.x * SCB;
    int t = threadIdx.x;
    int s = 0;
#pragma unroll
    for (int q = 0; q < 4; q++) {
        int i = base + t + q * 256;
        if (i < n) s += g_deg[i];
    }
#pragma unroll
    for (int o = 16; o; o >>= 1) s += __shfl_xor_sync(0xffffffffu, s, o);
    __shared__ int wt[8];
    if ((t & 31) == 0) wt[t >> 5] = s;
    __syncthreads();
    if (t == 0) {
        int tot = 0;
#pragma unroll
        for (int i = 0; i < 8; i++) tot += wt[i];
        g_bsum[blockIdx.x] = tot;
    }
}

// Phase 2: scan block sums (nb <= 128).
__global__ __launch_bounds__(128) void bscan_kernel(int nb, int n) {
    int t = threadIdx.x;
    int lane = t & 31, wid = t >> 5;
    int v = (t < nb) ? g_bsum[t] : 0;
    int incl = v;
#pragma unroll
    for (int o = 1; o < 32; o <<= 1) {
        int u = __shfl_up_sync(0xffffffffu, incl, o);
        if (lane >= o) incl += u;
    }
    __shared__ int wt[4];
    if (lane == 31) wt[wid] = incl;
    __syncthreads();
    if (t == 0) {
        int run = 0;
#pragma unroll
        for (int i = 0; i < 4; i++) { int u = wt[i]; wt[i] = run; run += u; }
    }
    __syncthreads();
    incl += wt[wid];
    if (t < nb) g_boff[t] = incl - v;
    if (t == nb - 1) g_rowptr[n] = incl;
}

// Phase 3: in-chunk exclusive scan + chunk offset -> rowptr & cursor.
__global__ __launch_bounds__(256) void scan_chunk_kernel(int n) {
    int base = blockIdx.x * SCB;
    int t = threadIdx.x;
    int i0 = base + t * 4;
    int d0 = (i0 + 0 < n) ? g_deg[i0 + 0] : 0;
    int d1 = (i0 + 1 < n) ? g_deg[i0 + 1] : 0;
    int d2 = (i0 + 2 < n) ? g_deg[i0 + 2] : 0;
    int d3 = (i0 + 3 < n) ? g_deg[i0 + 3] : 0;
    int s = d0 + d1 + d2 + d3;

    int lane = t & 31, wid = t >> 5;
    int incl = s;
#pragma unroll
    for (int o = 1; o < 32; o <<= 1) {
        int u = __shfl_up_sync(0xffffffffu, incl, o);
        if (lane >= o) incl += u;
    }
    __shared__ int wt[8];
    if (lane == 31) wt[wid] = incl;
    __syncthreads();
    if (t == 0) {
        int run = 0;
#pragma unroll
        for (int i = 0; i < 8; i++) { int u = wt[i]; wt[i] = run; run += u; }
    }
    __syncthreads();
    int run = incl - s + wt[wid] + g_boff[blockIdx.x];
    if (i0 + 0 < n) { g_rowptr[i0 + 0] = run; g_cursor[i0 + 0] = run; run += d0; }
    if (i0 + 1 < n) { g_rowptr[i0 + 1] = run; g_cursor[i0 + 1] = run; run += d1; }
    if (i0 + 2 < n) { g_rowptr[i0 + 2] = run; g_cursor[i0 + 2] = run; run += d2; }
    if (i0 + 3 < n) { g_rowptr[i0 + 3] = run; g_cursor[i0 + 3] = run; run += d3; }
}

__global__ void fill_kernel(const int* __restrict__ ei, int nE) {
    int e = blockIdx.x * blockDim.x + threadIdx.x;
    if (e >= nE) return;
    int s = ei[e];
    int d = ei[nE + e];
    int pos = atomicAdd(&g_cursor[d], 1);
    g_csrc[pos] = s;
}

// ---------------------------------------------------------------------------
// Layer 0 (fused): warp per node. Gather x[src] (mean), 3->128 linear + bias
// + ReLU + LayerNorm, all in-warp. Emits h in fp16.
// ---------------------------------------------------------------------------
__device__ __forceinline__ float warp_sum(float v) {
#pragma unroll
    for (int o = 16; o; o >>= 1) v += __shfl_xor_sync(0xffffffffu, v, o);
    return v;
}

__global__ __launch_bounds__(256) void layer0_kernel(
    const float* __restrict__ x, const float* __restrict__ Wl,
    const float* __restrict__ Wr, const float* __restrict__ b,
    const float* __restrict__ g, const float* __restrict__ be, int n) {
    int w = (blockIdx.x * blockDim.x + threadIdx.x) >> 5;
    if (w >= n) return;
    int lane = threadIdx.x & 31;
    int r0 = g_rowptr[w], r1 = g_rowptr[w + 1];

    float a0 = 0.f, a1 = 0.f, a2 = 0.f;
    for (int j = r0 + lane; j < r1; j += 32) {
        int s = g_csrc[j];
        a0 += x[3 * s];
        a1 += x[3 * s + 1];
        a2 += x[3 * s + 2];
    }
    a0 = warp_sum(a0); a1 = warp_sum(a1); a2 = warp_sum(a2);
    float inv = 1.f / fmaxf((float)(r1 - r0), 1.f);
    a0 *= inv; a1 *= inv; a2 *= inv;

    float x0 = x[3 * w], x1 = x[3 * w + 1], x2 = x[3 * w + 2];

    int col = lane * 4;
    float4 wl0 = *(const float4*)&Wl[0 * DG + col];
    float4 wl1 = *(const float4*)&Wl[1 * DG + col];
    float4 wl2 = *(const float4*)&Wl[2 * DG + col];
    float4 wr0 = *(const float4*)&Wr[0 * DG + col];
    float4 wr1 = *(const float4*)&Wr[1 * DG + col];
    float4 wr2 = *(const float4*)&Wr[2 * DG + col];
    float4 bv  = *(const float4*)&b[col];

    float v0 = bv.x + a0 * wl0.x + a1 * wl1.x + a2 * wl2.x + x0 * wr0.x + x1 * wr1.x + x2 * wr2.x;
    float v1 = bv.y + a0 * wl0.y + a1 * wl1.y + a2 * wl2.y + x0 * wr0.y + x1 * wr1.y + x2 * wr2.y;
    float v2 = bv.z + a0 * wl0.z + a1 * wl1.z + a2 * wl2.z + x0 * wr0.z + x1 * wr1.z + x2 * wr2.z;
    float v3 = bv.w + a0 * wl0.w + a1 * wl1.w + a2 * wl2.w + x0 * wr0.w + x1 * wr1.w + x2 * wr2.w;
    v0 = fmaxf(v0, 0.f); v1 = fmaxf(v1, 0.f); v2 = fmaxf(v2, 0.f); v3 = fmaxf(v3, 0.f);

    float mu = warp_sum(v0 + v1 + v2 + v3) * (1.f / DG);
    float d0 = v0 - mu, d1 = v1 - mu, d2 = v2 - mu, d3 = v3 - mu;
    float var = warp_sum(d0 * d0 + d1 * d1 + d2 * d2 + d3 * d3) * (1.f / DG);
    float rs = rsqrtf(var + 1e-5f);

    float4 gv = *(const float4*)&g[col];
    float4 bev = *(const float4*)&be[col];
    half2 p0 = __floats2half2_rn(d0 * rs * gv.x + bev.x, d1 * rs * gv.y + bev.y);
    half2 p1 = __floats2half2_rn(d2 * rs * gv.z + bev.z, d3 * rs * gv.w + bev.w);
    uint2 pk = make_uint2(*(uint32_t*)&p0, *(uint32_t*)&p1);
    *(uint2*)(g_hh + (size_t)w * DG + col) = pk;
}

// ---------------------------------------------------------------------------
// FUSED layer-1: gather (mean over in-edges of g_hh) into smem, then GEMM
// out = relu( [agg | h] @ Wfused + b1 ), K = 256, fp16 MMA m16n8k16.
// Block: 256 threads = 8 warps (4 wm x 2 wn). Tile M=64, N=128.
// Chunks of K=32; B (+A for h-part) double-buffered with register prefetch.
// ---------------------------------------------------------------------------
__global__ __launch_bounds__(256) void out_fused_kernel(
    const float* __restrict__ bias, float* __restrict__ out, int n) {
    __shared__ __align__(16) __half sAgg[64][136];      // 17408 B
    __shared__ __align__(16) __half sAh[2][64][40];     // 10240 B
    __shared__ __align__(16) __half sB[2][128][40];     // 20480 B -> 48128 B

    int tid = threadIdx.x;
    int wid = tid >> 5, lane = tid & 31;
    int wm = wid >> 1;        // 0..3 : rows wm*16 .. +15
    int wn = wid & 1;         // 0..1 : cols wn*64 .. +63
    int gid = lane >> 2, tg = lane & 3;
    int n0 = blockIdx.x * 64;

    // staging map (shared by B and A-h): row tid>>2, part tid&3
    int br = tid >> 2;        // 0..63
    int bp = tid & 3;         // 0..3

    // ---- prefetch B chunk 0 (issue LDG early, consume after gather) ----
    uint4 rb0 = *(const uint4*)(g_wh + (size_t)br * 256 + bp * 8);
    uint4 rb1 = *(const uint4*)(g_wh + (size_t)(br + 64) * 256 + bp * 8);

    // ---- gather phase: warp wid handles rows wid*8 .. wid*8+7 ----
    const uint2* hh = (const uint2*)g_hh;
#pragma unroll 1
    for (int i = 0; i < 8; i++) {
        int row = wid * 8 + i;
        int node = n0 + row;
        float ax = 0.f, ay = 0.f, az = 0.f, aw = 0.f;
        if (node < n) {
            int r0 = g_rowptr[node], r1 = g_rowptr[node + 1];
            int j = r0;
            for (; j + 8 <= r1; j += 8) {
                uint2 u[8];
#pragma unroll
                for (int q = 0; q < 8; q++) {
                    int s = g_csrc[j + q];
                    u[q] = hh[(size_t)s * 32 + lane];
                }
#pragma unroll
                for (int q = 0; q < 8; q++) {
                    float2 f0 = __half22float2(*(half2*)&u[q].x);
                    float2 f1 = __half22float2(*(half2*)&u[q].y);
                    ax += f0.x; ay += f0.y; az += f1.x; aw += f1.y;
                }
            }
            for (; j < r1; j++) {
                int s = g_csrc[j];
                uint2 uu = hh[(size_t)s * 32 + lane];
                float2 f0 = __half22float2(*(half2*)&uu.x);
                float2 f1 = __half22float2(*(half2*)&uu.y);
                ax += f0.x; ay += f0.y; az += f1.x; aw += f1.y;
            }
            float inv = 1.f / fmaxf((float)(r1 - r0), 1.f);
            ax *= inv; ay *= inv; az *= inv; aw *= inv;
        }
        half2 p0 = __floats2half2_rn(ax, ay);
        half2 p1 = __floats2half2_rn(az, aw);
        uint2 pk = make_uint2(*(uint32_t*)&p0, *(uint32_t*)&p1);
        *(uint2*)&sAgg[row][lane * 4] = pk;
    }

    // store B chunk 0
    *(uint4*)&sB[0][br][bp * 8] = rb0;
    *(uint4*)&sB[0][br + 64][bp * 8] = rb1;
    __syncthreads();

    float acc[8][4];
#pragma unroll
    for (int nt = 0; nt < 8; nt++)
#pragma unroll
        for (int i = 0; i < 4; i++) acc[nt][i] = 0.f;

    uint4 ra = make_uint4(0, 0, 0, 0);

#pragma unroll 1
    for (int c = 0; c < 8; c++) {
        // prefetch next chunk into registers (overlaps with MMA below)
        if (c < 7) {
            int cn = c + 1;
            rb0 = *(const uint4*)(g_wh + (size_t)br * 256 + cn * 32 + bp * 8);
            rb1 = *(const uint4*)(g_wh + (size_t)(br + 64) * 256 + cn * 32 + bp * 8);
            if (cn >= 4) {
                ra = make_uint4(0, 0, 0, 0);
                if (n0 + br < n)
                    ra = *(const uint4*)(g_hh + (size_t)(n0 + br) * DG + (cn - 4) * 32 + bp * 8);
            }
        }

        // compute chunk c: 2 k16 steps
#pragma unroll
        for (int ks = 0; ks < 2; ks++) {
            int ko = ks * 16;
            uint32_t bf0[8], bf1[8];
#pragma unroll
            for (int nt = 0; nt < 8; nt++) {
                int ncol = wn * 64 + nt * 8 + gid;
                bf0[nt] = *(uint32_t*)&sB[c & 1][ncol][ko + 2 * tg];
                bf1[nt] = *(uint32_t*)&sB[c & 1][ncol][ko + 2 * tg + 8];
            }
            int r = wm * 16 + gid;
            uint32_t a0, a1, a2, a3;
            if (c < 4) {
                int cb = c * 32 + ko;
                a0 = *(uint32_t*)&sAgg[r][cb + 2 * tg];
                a1 = *(uint32_t*)&sAgg[r + 8][cb + 2 * tg];
                a2 = *(uint32_t*)&sAgg[r][cb + 2 * tg + 8];
                a3 = *(uint32_t*)&sAgg[r + 8][cb + 2 * tg + 8];
            } else {
                a0 = *(uint32_t*)&sAh[c & 1][r][ko + 2 * tg];
                a1 = *(uint32_t*)&sAh[c & 1][r + 8][ko + 2 * tg];
                a2 = *(uint32_t*)&sAh[c & 1][r][ko + 2 * tg + 8];
                a3 = *(uint32_t*)&sAh[c & 1][r + 8][ko + 2 * tg + 8];
            }
#pragma unroll
            for (int nt = 0; nt < 8; nt++) {
                asm volatile(
                    "mma.sync.aligned.m16n8k16.row.col.f32.f16.f16.f32 "
                    "{%0,%1,%2,%3}, {%4,%5,%6,%7}, {%8,%9}, {%0,%1,%2,%3};"
                    : "+f"(acc[nt][0]), "+f"(acc[nt][1]),
                      "+f"(acc[nt][2]), "+f"(acc[nt][3])
                    : "r"(a0), "r"(a1), "r"(a2), "r"(a3),
                      "r"(bf0[nt]), "r"(bf1[nt]));
            }
        }

        // store prefetched chunk into the other buffer
        if (c < 7) {
            int cn = c + 1;
            *(uint4*)&sB[cn & 1][br][bp * 8] = rb0;
            *(uint4*)&sB[cn & 1][br + 64][bp * 8] = rb1;
            if (cn >= 4)
                *(uint4*)&sAh[cn & 1][br][bp * 8] = ra;
            __syncthreads();
        }
    }

    // ---- epilogue: bias + relu, float2 stores ----
#pragma unroll
    for (int nt = 0; nt < 8; nt++) {
        int col = wn * 64 + nt * 8 + 2 * tg;
        float2 bv = *(const float2*)&bias[col];
        int row = n0 + wm * 16 + gid;
        if (row < n) {
            float2 o;
            o.x = fmaxf(acc[nt][0] + bv.x, 0.f);
            o.y = fmaxf(acc[nt][1] + bv.y, 0.f);
            *(float2*)&out[(size_t)row * DG + col] = o;
        }
        if (row + 8 < n) {
            float2 o;
            o.x = fmaxf(acc[nt][2] + bv.x, 0.f);
            o.y = fmaxf(acc[nt][3] + bv.y, 0.f);
            *(float2*)&out[(size_t)(row + 8) * DG + col] = o;
        }
    }
}

// ---------------------------------------------------------------------------
extern "C" void kernel_launch(void* const* d_in, const int* in_sizes, int n_in,
                              void* d_out, int out_size) {
    const float* x   = (const float*)d_in[0];
    const int*   ei  = (const int*)d_in[1];
    const float* Wl0 = (const float*)d_in[2];
    const float* Wr0 = (const float*)d_in[3];
    const float* b0  = (const float*)d_in[4];
    const float* Wl1 = (const float*)d_in[5];
    const float* Wr1 = (const float*)d_in[6];
    const float* b1  = (const float*)d_in[7];
    const float* g   = (const float*)d_in[8];
    const float* be  = (const float*)d_in[9];
    float* out = (float*)d_out;

    int n  = in_sizes[0] / 3;
    int nE = in_sizes[1] / 2;
    int nb = (n + SCB - 1) / SCB;
    int prepN = (n > 2 * DG * DG) ? n : 2 * DG * DG;

    prep_kernel<<<(prepN + 255) / 256, 256>>>(Wl1, Wr1, n);
    hist_kernel<<<(nE + 255) / 256, 256>>>(ei, nE);
    bsum_kernel<<<nb, 256>>>(n);
    bscan_kernel<<<1, 128>>>(nb, n);
    scan_chunk_kernel<<<nb, 256>>>(n);
    fill_kernel<<<(nE + 255) / 256, 256>>>(ei, nE);
    layer0_kernel<<<(n * 32 + 255) / 256, 256>>>(x, Wl0, Wr0, b0, g, be, n);
    out_fused_kernel<<<(n + 63) / 64, 256>>>(b1, out, n);
}

// round 10
// speedup vs baseline: 1.2035x; 1.2035x over previous
#include <cuda_runtime.h>
#include <cuda_fp16.h>
#include <cstdint>

#define DG 128
#define MAXN 100000
#define MAXE 1600000
#define SCB 1024
#define MAXB ((MAXN + SCB - 1) / SCB)

// Scratch (device globals — no allocation allowed).
__device__ int g_deg[MAXN];
__device__ int g_rowptr[MAXN + 1];
__device__ int g_cursor[MAXN];
__device__ int g_csrc[MAXE];
__device__ int g_bsum[MAXB];
__device__ int g_boff[MAXB];
__device__ __align__(16) __half g_hh[MAXN * DG];    // h after layer0+LN (fp16)
__device__ __align__(16) __half g_aggh[MAXN * DG];  // layer1 mean-agg (fp16)
__device__ __align__(16) __half g_wh[2 * DG * DG];  // [n][k] fp16 fused weights

// ---------------------------------------------------------------------------
// Prep: zero degree array + fuse/convert weights (merged kernel)
// ---------------------------------------------------------------------------
__global__ void prep_kernel(const float* __restrict__ Wl,
                            const float* __restrict__ Wr, int n) {
    int t = blockIdx.x * blockDim.x + threadIdx.x;
    if (t < 2 * DG * DG) {
        int k = t >> 7, nn = t & 127;
        float v = (k < DG) ? Wl[k * DG + nn] : Wr[(k - DG) * DG + nn];
        g_wh[nn * 2 * DG + k] = __float2half_rn(v);
    }
    if (t < n) g_deg[t] = 0;
}

__global__ void hist_kernel(const int* __restrict__ ei, int nE) {
    int e = blockIdx.x * blockDim.x + threadIdx.x;
    if (e < nE) atomicAdd(&g_deg[ei[nE + e]], 1);
}

// Phase 1: per-chunk sums.
__global__ __launch_bounds__(256) void bsum_kernel(int n) {
    int base = blockIdx.x * SCB;
    int t = threadIdx.x;
    int s = 0;
#pragma unroll
    for (int q = 0; q < 4; q++) {
        int i = base + t + q * 256;
        if (i < n) s += g_deg[i];
    }
#pragma unroll
    for (int o = 16; o; o >>= 1) s += __shfl_xor_sync(0xffffffffu, s, o);
    __shared__ int wt[8];
    if ((t & 31) == 0) wt[t >> 5] = s;
    __syncthreads();
    if (t == 0) {
        int tot = 0;
#pragma unroll
        for (int i = 0; i < 8; i++) tot += wt[i];
        g_bsum[blockIdx.x] = tot;
    }
}

// Phase 2: scan block sums (nb <= 128).
__global__ __launch_bounds__(128) void bscan_kernel(int nb, int n) {
    int t = threadIdx.x;
    int lane = t & 31, wid = t >> 5;
    int v = (t < nb) ? g_bsum[t] : 0;
    int incl = v;
#pragma unroll
    for (int o = 1; o < 32; o <<= 1) {
        int u = __shfl_up_sync(0xffffffffu, incl, o);
        if (lane >= o) incl += u;
    }
    __shared__ int wt[4];
    if (lane == 31) wt[wid] = incl;
    __syncthreads();
    if (t == 0) {
        int run = 0;
#pragma unroll
        for (int i = 0; i < 4; i++) { int u = wt[i]; wt[i] = run; run += u; }
    }
    __syncthreads();
    incl += wt[wid];
    if (t < nb) g_boff[t] = incl - v;
    if (t == nb - 1) g_rowptr[n] = incl;
}

// Phase 3: in-chunk exclusive scan + chunk offset -> rowptr & cursor.
__global__ __launch_bounds__(256) void scan_chunk_kernel(int n) {
    int base = blockIdx.x * SCB;
    int t = threadIdx.x;
    int i0 = base + t * 4;
    int d0 = (i0 + 0 < n) ? g_deg[i0 + 0] : 0;
    int d1 = (i0 + 1 < n) ? g_deg[i0 + 1] : 0;
    int d2 = (i0 + 2 < n) ? g_deg[i0 + 2] : 0;
    int d3 = (i0 + 3 < n) ? g_deg[i0 + 3] : 0;
    int s = d0 + d1 + d2 + d3;

    int lane = t & 31, wid = t >> 5;
    int incl = s;
#pragma unroll
    for (int o = 1; o < 32; o <<= 1) {
        int u = __shfl_up_sync(0xffffffffu, incl, o);
        if (lane >= o) incl += u;
    }
    __shared__ int wt[8];
    if (lane == 31) wt[wid] = incl;
    __syncthreads();
    if (t == 0) {
        int run = 0;
#pragma unroll
        for (int i = 0; i < 8; i++) { int u = wt[i]; wt[i] = run; run += u; }
    }
    __syncthreads();
    int run = incl - s + wt[wid] + g_boff[blockIdx.x];
    if (i0 + 0 < n) { g_rowptr[i0 + 0] = run; g_cursor[i0 + 0] = run; run += d0; }
    if (i0 + 1 < n) { g_rowptr[i0 + 1] = run; g_cursor[i0 + 1] = run; run += d1; }
    if (i0 + 2 < n) { g_rowptr[i0 + 2] = run; g_cursor[i0 + 2] = run; run += d2; }
    if (i0 + 3 < n) { g_rowptr[i0 + 3] = run; g_cursor[i0 + 3] = run; run += d3; }
}

__global__ void fill_kernel(const int* __restrict__ ei, int nE) {
    int e = blockIdx.x * blockDim.x + threadIdx.x;
    if (e >= nE) return;
    int s = ei[e];
    int d = ei[nE + e];
    int pos = atomicAdd(&g_cursor[d], 1);
    g_csrc[pos] = s;
}

// ---------------------------------------------------------------------------
// Layer 0 (fused): warp per node. Gather x[src] (mean), 3->128 linear + bias
// + ReLU + LayerNorm, all in-warp. Emits h in fp16.
// ---------------------------------------------------------------------------
__device__ __forceinline__ float warp_sum(float v) {
#pragma unroll
    for (int o = 16; o; o >>= 1) v += __shfl_xor_sync(0xffffffffu, v, o);
    return v;
}

__global__ __launch_bounds__(256) void layer0_kernel(
    const float* __restrict__ x, const float* __restrict__ Wl,
    const float* __restrict__ Wr, const float* __restrict__ b,
    const float* __restrict__ g, const float* __restrict__ be, int n) {
    int w = (blockIdx.x * blockDim.x + threadIdx.x) >> 5;
    if (w >= n) return;
    int lane = threadIdx.x & 31;
    int r0 = g_rowptr[w], r1 = g_rowptr[w + 1];

    float a0 = 0.f, a1 = 0.f, a2 = 0.f;
    for (int j = r0 + lane; j < r1; j += 32) {
        int s = g_csrc[j];
        a0 += x[3 * s];
        a1 += x[3 * s + 1];
        a2 += x[3 * s + 2];
    }
    a0 = warp_sum(a0); a1 = warp_sum(a1); a2 = warp_sum(a2);
    float inv = 1.f / fmaxf((float)(r1 - r0), 1.f);
    a0 *= inv; a1 *= inv; a2 *= inv;

    float x0 = x[3 * w], x1 = x[3 * w + 1], x2 = x[3 * w + 2];

    int col = lane * 4;
    float4 wl0 = *(const float4*)&Wl[0 * DG + col];
    float4 wl1 = *(const float4*)&Wl[1 * DG + col];
    float4 wl2 = *(const float4*)&Wl[2 * DG + col];
    float4 wr0 = *(const float4*)&Wr[0 * DG + col];
    float4 wr1 = *(const float4*)&Wr[1 * DG + col];
    float4 wr2 = *(const float4*)&Wr[2 * DG + col];
    float4 bv  = *(const float4*)&b[col];

    float v0 = bv.x + a0 * wl0.x + a1 * wl1.x + a2 * wl2.x + x0 * wr0.x + x1 * wr1.x + x2 * wr2.x;
    float v1 = bv.y + a0 * wl0.y + a1 * wl1.y + a2 * wl2.y + x0 * wr0.y + x1 * wr1.y + x2 * wr2.y;
    float v2 = bv.z + a0 * wl0.z + a1 * wl1.z + a2 * wl2.z + x0 * wr0.z + x1 * wr1.z + x2 * wr2.z;
    float v3 = bv.w + a0 * wl0.w + a1 * wl1.w + a2 * wl2.w + x0 * wr0.w + x1 * wr1.w + x2 * wr2.w;
    v0 = fmaxf(v0, 0.f); v1 = fmaxf(v1, 0.f); v2 = fmaxf(v2, 0.f); v3 = fmaxf(v3, 0.f);

    float mu = warp_sum(v0 + v1 + v2 + v3) * (1.f / DG);
    float d0 = v0 - mu, d1 = v1 - mu, d2 = v2 - mu, d3 = v3 - mu;
    float var = warp_sum(d0 * d0 + d1 * d1 + d2 * d2 + d3 * d3) * (1.f / DG);
    float rs = rsqrtf(var + 1e-5f);

    float4 gv = *(const float4*)&g[col];
    float4 bev = *(const float4*)&be[col];
    half2 p0 = __floats2half2_rn(d0 * rs * gv.x + bev.x, d1 * rs * gv.y + bev.y);
    half2 p1 = __floats2half2_rn(d2 * rs * gv.z + bev.z, d3 * rs * gv.w + bev.w);
    uint2 pk = make_uint2(*(uint32_t*)&p0, *(uint32_t*)&p1);
    *(uint2*)(g_hh + (size_t)w * DG + col) = pk;
}

// ---------------------------------------------------------------------------
// Layer 1 aggregation: 16 lanes per node (2 nodes/warp), uint4 (16B) loads —
// each LDG instruction moves 512B across the warp (2x fewer issues than uint2).
// fp32 accumulate, 4-way unroll; inv_deg applied; result stored fp16.
// ---------------------------------------------------------------------------
__global__ __launch_bounds__(256) void agg_kernel(int n) {
    int gw = (blockIdx.x * blockDim.x + threadIdx.x) >> 5;
    int lane = threadIdx.x & 31;
    int node = gw * 2 + (lane >> 4);
    if (node >= n) return;
    int l16 = lane & 15;
    int r0 = g_rowptr[node], r1 = g_rowptr[node + 1];
    const uint4* hh = (const uint4*)g_hh;   // 16 uint4 per node row

    float a0 = 0.f, a1 = 0.f, a2 = 0.f, a3 = 0.f;
    float a4 = 0.f, a5 = 0.f, a6 = 0.f, a7 = 0.f;
    int j = r0;
    for (; j + 4 <= r1; j += 4) {
        uint4 u[4];
#pragma unroll
        for (int q = 0; q < 4; q++) {
            int s = g_csrc[j + q];
            u[q] = hh[(size_t)s * 16 + l16];
        }
#pragma unroll
        for (int q = 0; q < 4; q++) {
            float2 f0 = __half22float2(*(half2*)&u[q].x);
            float2 f1 = __half22float2(*(half2*)&u[q].y);
            float2 f2 = __half22float2(*(half2*)&u[q].z);
            float2 f3 = __half22float2(*(half2*)&u[q].w);
            a0 += f0.x; a1 += f0.y; a2 += f1.x; a3 += f1.y;
            a4 += f2.x; a5 += f2.y; a6 += f3.x; a7 += f3.y;
        }
    }
    for (; j < r1; j++) {
        int s = g_csrc[j];
        uint4 u = hh[(size_t)s * 16 + l16];
        float2 f0 = __half22float2(*(half2*)&u.x);
        float2 f1 = __half22float2(*(half2*)&u.y);
        float2 f2 = __half22float2(*(half2*)&u.z);
        float2 f3 = __half22float2(*(half2*)&u.w);
        a0 += f0.x; a1 += f0.y; a2 += f1.x; a3 += f1.y;
        a4 += f2.x; a5 += f2.y; a6 += f3.x; a7 += f3.y;
    }
    float inv = 1.f / fmaxf((float)(r1 - r0), 1.f);
    half2 p0 = __floats2half2_rn(a0 * inv, a1 * inv);
    half2 p1 = __floats2half2_rn(a2 * inv, a3 * inv);
    half2 p2 = __floats2half2_rn(a4 * inv, a5 * inv);
    half2 p3 = __floats2half2_rn(a6 * inv, a7 * inv);
    uint4 pk = make_uint4(*(uint32_t*)&p0, *(uint32_t*)&p1,
                          *(uint32_t*)&p2, *(uint32_t*)&p3);
    ((uint4*)g_aggh)[(size_t)node * 16 + l16] = pk;
}

// ---------------------------------------------------------------------------
// Layer 1 output GEMM + relu, fp16 tensor cores (mma.sync m16n8k16, f32 acc).
// Block: 256 threads = 8 warps (4x2). Tile M=128, N=128. K chunked by 32.
// ---------------------------------------------------------------------------
#define KB 32
#define ASTR 40
__global__ __launch_bounds__(256) void out_kernel(
    const float* __restrict__ bias, float* __restrict__ out, int n) {
    __shared__ __align__(16) __half sA[128][ASTR];
    __shared__ __align__(16) __half sB[128][ASTR];

    int tid = threadIdx.x;
    int wid = tid >> 5;
    int lane = tid & 31;
    int wm = wid >> 1;
    int wn = wid & 1;
    int gid = lane >> 2;
    int tg = lane & 3;
    int n0 = blockIdx.x * 128;

    float acc[2][8][4];
#pragma unroll
    for (int mt = 0; mt < 2; mt++)
#pragma unroll
        for (int nt = 0; nt < 8; nt++)
#pragma unroll
            for (int i = 0; i < 4; i++) acc[mt][nt][i] = 0.f;

    for (int kc = 0; kc < 2 * DG; kc += KB) {
        __syncthreads();
        {
            const __half* src = (kc < DG) ? g_aggh : g_hh;
            int ka = kc & (DG - 1);
#pragma unroll
            for (int q = 0; q < 2; q++) {
                int idx = tid + q * 256;
                int r = idx >> 2;
                int part = idx & 3;
                uint4 v = make_uint4(0, 0, 0, 0);
                if (n0 + r < n)
                    v = *(const uint4*)(src + (size_t)(n0 + r) * DG + ka + part * 8);
                *(uint4*)&sA[r][part * 8] = v;
            }
        }
        {
#pragma unroll
            for (int q = 0; q < 2; q++) {
                int idx = tid + q * 256;
                int r = idx >> 2;
                int part = idx & 3;
                uint4 v = *(const uint4*)(g_wh + (size_t)r * 2 * DG + kc + part * 8);
                *(uint4*)&sB[r][part * 8] = v;
            }
        }
        __syncthreads();

#pragma unroll
        for (int ks = 0; ks < 2; ks++) {
            int ko = ks * 16;
            uint32_t bf[8][2];
#pragma unroll
            for (int nt = 0; nt < 8; nt++) {
                int ncol = wn * 64 + nt * 8 + gid;
                bf[nt][0] = *(uint32_t*)&sB[ncol][ko + 2 * tg];
                bf[nt][1] = *(uint32_t*)&sB[ncol][ko + 2 * tg + 8];
            }
#pragma unroll
            for (int mt = 0; mt < 2; mt++) {
                int r = wm * 32 + mt * 16 + gid;
                uint32_t a0 = *(uint32_t*)&sA[r][ko + 2 * tg];
                uint32_t a1 = *(uint32_t*)&sA[r + 8][ko + 2 * tg];
                uint32_t a2 = *(uint32_t*)&sA[r][ko + 2 * tg + 8];
                uint32_t a3 = *(uint32_t*)&sA[r + 8][ko + 2 * tg + 8];
#pragma unroll
                for (int nt = 0; nt < 8; nt++) {
                    asm volatile(
                        "mma.sync.aligned.m16n8k16.row.col.f32.f16.f16.f32 "
                        "{%0,%1,%2,%3}, {%4,%5,%6,%7}, {%8,%9}, {%0,%1,%2,%3};"
                        : "+f"(acc[mt][nt][0]), "+f"(acc[mt][nt][1]),
                          "+f"(acc[mt][nt][2]), "+f"(acc[mt][nt][3])
                        : "r"(a0), "r"(a1), "r"(a2), "r"(a3),
                          "r"(bf[nt][0]), "r"(bf[nt][1]));
                }
            }
        }
    }

#pragma unroll
    for (int nt = 0; nt < 8; nt++) {
        int col = wn * 64 + nt * 8 + 2 * tg;
        float2 bv = *(const float2*)&bias[col];
#pragma unroll
        for (int mt = 0; mt < 2; mt++) {
            int row = n0 + wm * 32 + mt * 16 + gid;
            if (row < n) {
                float2 o;
                o.x = fmaxf(acc[mt][nt][0] + bv.x, 0.f);
                o.y = fmaxf(acc[mt][nt][1] + bv.y, 0.f);
                *(float2*)&out[(size_t)row * DG + col] = o;
            }
            if (row + 8 < n) {
                float2 o;
                o.x = fmaxf(acc[mt][nt][2] + bv.x, 0.f);
                o.y = fmaxf(acc[mt][nt][3] + bv.y, 0.f);
                *(float2*)&out[(size_t)(row + 8) * DG + col] = o;
            }
        }
    }
}

// ---------------------------------------------------------------------------
extern "C" void kernel_launch(void* const* d_in, const int* in_sizes, int n_in,
                              void* d_out, int out_size) {
    const float* x   = (const float*)d_in[0];
    const int*   ei  = (const int*)d_in[1];
    const float* Wl0 = (const float*)d_in[2];
    const float* Wr0 = (const float*)d_in[3];
    const float* b0  = (const float*)d_in[4];
    const float* Wl1 = (const float*)d_in[5];
    const float* Wr1 = (const float*)d_in[6];
    const float* b1  = (const float*)d_in[7];
    const float* g   = (const float*)d_in[8];
    const float* be  = (const float*)d_in[9];
    float* out = (float*)d_out;

    int n  = in_sizes[0] / 3;
    int nE = in_sizes[1] / 2;
    int nb = (n + SCB - 1) / SCB;
    int prepN = (n > 2 * DG * DG) ? n : 2 * DG * DG;

    prep_kernel<<<(prepN + 255) / 256, 256>>>(Wl1, Wr1, n);
    hist_kernel<<<(nE + 255) / 256, 256>>>(ei, nE);
    bsum_kernel<<<nb, 256>>>(n);
    bscan_kernel<<<1, 128>>>(nb, n);
    scan_chunk_kernel<<<nb, 256>>>(n);
    fill_kernel<<<(nE + 255) / 256, 256>>>(ei, nE);
    layer0_kernel<<<(n * 32 + 255) / 256, 256>>>(x, Wl0, Wr0, b0, g, be, n);
    int aggWarps = (n + 1) / 2;
    agg_kernel<<<(aggWarps * 32 + 255) / 256, 256>>>(n);
    out_kernel<<<(n + 127) / 128, 256>>>(b1, out, n);
}